// round 14
// baseline (speedup 1.0000x reference)
#include <cuda_runtime.h>

#define BB 32
#define SS 2048
#define NROWS (BB * SS)
#define NSPLIT 16

// Scratch: __device__ globals (no allocation allowed in kernel_launch).
__device__ float4 g_Q[NROWS];            // pre-scaled by 0.5*log2(e)
// Pair-packed layouts: for key pair p (rows 2p, 2p+1):
//   g_Kp[2p]   = (k0.x, k1.x, k0.y, k1.y)
//   g_Kp[2p+1] = (k0.z, k1.z, k0.w, k1.w)
__device__ float4 g_Kp[NROWS];
__device__ float4 g_Vp[NROWS];
__device__ float4 g_pnum[NSPLIT * NROWS];  // partial sum(e*V)
__device__ float  g_pden[NSPLIT * NROWS];  // partial sum(e)

typedef unsigned long long ull;

// ---------------------------------------------------------------------------
// Packed f32x2 helpers (sm_103a FFMA2 path — ptxas won't auto-fuse from C++)
// ---------------------------------------------------------------------------
__device__ __forceinline__ ull pack2(float lo, float hi) {
    ull r; asm("mov.b64 %0, {%1, %2};" : "=l"(r) : "f"(lo), "f"(hi)); return r;
}
__device__ __forceinline__ void unpack2(ull v, float& lo, float& hi) {
    asm("mov.b64 {%0, %1}, %2;" : "=f"(lo), "=f"(hi) : "l"(v));
}
__device__ __forceinline__ ull fma2(ull a, ull b, ull c) {
    ull d; asm("fma.rn.f32x2 %0, %1, %2, %3;" : "=l"(d) : "l"(a), "l"(b), "l"(c)); return d;
}
__device__ __forceinline__ ull mul2(ull a, ull b) {
    ull d; asm("mul.rn.f32x2 %0, %1, %2;" : "=l"(d) : "l"(a), "l"(b)); return d;
}
__device__ __forceinline__ ull add2(ull a, ull b) {
    ull d; asm("add.rn.f32x2 %0, %1, %2;" : "=l"(d) : "l"(a), "l"(b)); return d;
}
__device__ __forceinline__ float fast_exp2(float x) {
    float y; asm("ex2.approx.ftz.f32 %0, %1;" : "=f"(y) : "f"(x)); return y;
}

// ---------------------------------------------------------------------------
// 16-dim statevector circuit: qubit q lives at bit (3-q). Fully unrolled;
// CNOTs are free register renames.
// ---------------------------------------------------------------------------
template <int Q>
__device__ __forceinline__ void rx_gate(float sr[16], float si[16], float c, float sn) {
    const int m = 1 << (3 - Q);
#pragma unroll
    for (int i = 0; i < 16; i++) {
        if (!(i & m)) {
            const int j = i | m;
            float a0r = sr[i], a0i = si[i];
            float a1r = sr[j], a1i = si[j];
            sr[i] = c * a0r + sn * a1i;
            si[i] = c * a0i - sn * a1r;
            sr[j] = c * a1r + sn * a0i;
            si[j] = c * a1i - sn * a0r;
        }
    }
}

template <int Q>
__device__ __forceinline__ void cnot_gate(float sr[16], float si[16]) {
    const int cm = 1 << (3 - Q);
    const int tm = 1 << (3 - ((Q + 1) & 3));
#pragma unroll
    for (int i = 0; i < 16; i++) {
        if ((i & cm) && !(i & tm)) {
            const int j = i | tm;
            float t;
            t = sr[i]; sr[i] = sr[j]; sr[j] = t;
            t = si[i]; si[i] = si[j]; si[j] = t;
        }
    }
}

__device__ __forceinline__ float4 measure(const float sr[16], const float si[16]) {
    float e0 = 0.f, e1 = 0.f, e2 = 0.f, e3 = 0.f;
#pragma unroll
    for (int i = 0; i < 16; i++) {
        float p = sr[i] * sr[i] + si[i] * si[i];
        e0 += (i & 8) ? -p : p;
        e1 += (i & 4) ? -p : p;
        e2 += (i & 2) ? -p : p;
        e3 += (i & 1) ? -p : p;
    }
    return make_float4(e0, e1, e2, e3);
}

__device__ __forceinline__ float4 layer_and_measure(
    const float er[16], const float ei[16],
    const float wc[4], const float ws[4])
{
    float sr[16], si[16];
#pragma unroll
    for (int i = 0; i < 16; i++) { sr[i] = er[i]; si[i] = ei[i]; }

    rx_gate<0>(sr, si, wc[0], ws[0]);
    rx_gate<1>(sr, si, wc[1], ws[1]);
    rx_gate<2>(sr, si, wc[2], ws[2]);
    rx_gate<3>(sr, si, wc[3], ws[3]);
    cnot_gate<0>(sr, si);
    cnot_gate<1>(sr, si);
    cnot_gate<2>(sr, si);
    cnot_gate<3>(sr, si);
    return measure(sr, si);
}

// MUFU-based sincos: half-angles are small (x ~ N(0,1)*0.5, ctx in [-0.5,0.5])
// so __sincosf accuracy is far inside the 1e-3 tolerance.
__device__ __forceinline__ void embed(float4 ang, float er[16], float ei[16]) {
#pragma unroll
    for (int i = 0; i < 16; i++) { er[i] = 0.f; ei[i] = 0.f; }
    er[0] = 1.f;
    float c, sn;
    __sincosf(ang.x * 0.5f, &sn, &c); rx_gate<0>(er, ei, c, sn);
    __sincosf(ang.y * 0.5f, &sn, &c); rx_gate<1>(er, ei, c, sn);
    __sincosf(ang.z * 0.5f, &sn, &c); rx_gate<2>(er, ei, c, sn);
    __sincosf(ang.w * 0.5f, &sn, &c); rx_gate<3>(er, ei, c, sn);
}

// Weights: half-angles in [0, pi] — __sincosf abs error far inside tolerance.
__device__ __forceinline__ void load_w(const float* __restrict__ w, float wc[4], float ws[4]) {
#pragma unroll
    for (int i = 0; i < 4; i++) __sincosf(w[i] * 0.5f, &ws[i], &wc[i]);
}

// ---------------------------------------------------------------------------
// Kernel 1: x -> Q | K | V, one circuit per blockIdx.y (3x warp parallelism
// for ~1.3x work; embed re-computed per circuit but constant-folds from |0>).
// ---------------------------------------------------------------------------
__global__ void __launch_bounds__(128)
qkv_kernel(const float4* __restrict__ x,
           const float* __restrict__ wQ,
           const float* __restrict__ wK,
           const float* __restrict__ wV)
{
    const int idx   = blockIdx.x * blockDim.x + threadIdx.x;
    const int which = blockIdx.y;          // 0=Q, 1=K, 2=V
    if (idx >= NROWS) return;

    float er[16], ei[16];
    embed(x[idx], er, ei);

    const float* w = (which == 0) ? wQ : (which == 1) ? wK : wV;
    float wc[4], ws[4];
    load_w(w, wc, ws);

    float4 r = layer_and_measure(er, ei, wc, ws);

    if (which == 0) {
        const float scale = 0.5f * 1.4426950408889634f;  // 1/sqrt(E)*log2(e)
        r.x *= scale; r.y *= scale; r.z *= scale; r.w *= scale;
        g_Q[idx] = r;
    } else {
        const int p = idx >> 1;
        const int h = idx & 1;
        float* g = (which == 1) ? (float*)g_Kp : (float*)g_Vp;
        g[p * 8 + 0 + h] = r.x;
        g[p * 8 + 2 + h] = r.y;
        g[p * 8 + 4 + h] = r.z;
        g[p * 8 + 6 + h] = r.w;
    }
}

// ---------------------------------------------------------------------------
// Kernel 2: split-K flash attention partials (R10 config: TPB=128, QPT=2,
// NSPLIT=16) + register-level software pipelining: iteration p+1's K/V LDS
// issues during iteration p's FMA/EX2 work, so the 29-cyc LDS latency is
// never the binding scoreboard arm. K and V live in ONE contiguous SMEM
// array so the prologue's one-past-end prefetch stays in-bounds.
// Raw exp2 softmax (scores in [-2.9,2.9]): partials combine exactly by sum.
// ---------------------------------------------------------------------------
#define ATTN_TPB   128
#define KEYS_SPLIT (SS / NSPLIT)        // 128 keys = 128 packed float4

__global__ void __launch_bounds__(ATTN_TPB)
attn_kernel()
{
    __shared__ float4 sKV[2 * KEYS_SPLIT];   // [0,128): K  [128,256): V

    const int b     = blockIdx.y;
    const int split = blockIdx.z;
    const int t     = threadIdx.x;
    const int qrow  = b * SS + blockIdx.x * (ATTN_TPB * 2) + t;

    // Stage this split's K/V slice.
    if (t < KEYS_SPLIT) {
        sKV[t]              = g_Kp[b * SS + split * KEYS_SPLIT + t];
        sKV[KEYS_SPLIT + t] = g_Vp[b * SS + split * KEYS_SPLIT + t];
    }

    float4 qa = g_Q[qrow];
    float4 qb = g_Q[qrow + ATTN_TPB];

    const ull qa_x = pack2(qa.x, qa.x), qa_y = pack2(qa.y, qa.y);
    const ull qa_z = pack2(qa.z, qa.z), qa_w = pack2(qa.w, qa.w);
    const ull qb_x = pack2(qb.x, qb.x), qb_y = pack2(qb.y, qb.y);
    const ull qb_z = pack2(qb.z, qb.z), qb_w = pack2(qb.w, qb.w);

    ull den_a = 0, den_b = 0;
    ull aa0 = 0, aa1 = 0, aa2 = 0, aa3 = 0;
    ull ab0 = 0, ab1 = 0, ab2 = 0, ab3 = 0;

    __syncthreads();

    const ulonglong2* kk = (const ulonglong2*)sKV;                 // 64 entries
    const ulonglong2* vv = (const ulonglong2*)(sKV + KEYS_SPLIT);  // 64 entries

    // Software pipeline: prefetch registers one iteration ahead.
    ulonglong2 ka = kk[0], kb = kk[1];
    ulonglong2 va = vv[0], vb = vv[1];

#pragma unroll 8
    for (int p = 0; p < KEYS_SPLIT / 2; p++) {
        // Prefetch next iteration (p = last reads kk[64] = vv[0] and
        // vv[64] = one past V, still inside the 8KB sKV+guard? No guard
        // needed: vv[64] == sKV[256] is out of the array, so clamp).
        const int pn = (p + 1 < KEYS_SPLIT / 2) ? (p + 1) : 0;
        ulonglong2 ka_n = kk[2 * pn], kb_n = kk[2 * pn + 1];
        ulonglong2 va_n = vv[2 * pn], vb_n = vv[2 * pn + 1];

        ull sa = fma2(qa_x, ka.x, fma2(qa_y, ka.y, fma2(qa_z, kb.x, mul2(qa_w, kb.y))));
        ull sb = fma2(qb_x, ka.x, fma2(qb_y, ka.y, fma2(qb_z, kb.x, mul2(qb_w, kb.y))));

        float s0, s1;
        unpack2(sa, s0, s1);
        ull ea = pack2(fast_exp2(s0), fast_exp2(s1));
        unpack2(sb, s0, s1);
        ull eb = pack2(fast_exp2(s0), fast_exp2(s1));

        den_a = add2(den_a, ea);
        den_b = add2(den_b, eb);

        aa0 = fma2(ea, va.x, aa0);
        aa1 = fma2(ea, va.y, aa1);
        aa2 = fma2(ea, vb.x, aa2);
        aa3 = fma2(ea, vb.y, aa3);
        ab0 = fma2(eb, va.x, ab0);
        ab1 = fma2(eb, va.y, ab1);
        ab2 = fma2(eb, vb.x, ab2);
        ab3 = fma2(eb, vb.y, ab3);

        ka = ka_n; kb = kb_n; va = va_n; vb = vb_n;
    }

    const int base = split * NROWS;
    {
        float d0, d1, u0, u1;
        float4 num;
        unpack2(aa0, u0, u1); num.x = u0 + u1;
        unpack2(aa1, u0, u1); num.y = u0 + u1;
        unpack2(aa2, u0, u1); num.z = u0 + u1;
        unpack2(aa3, u0, u1); num.w = u0 + u1;
        unpack2(den_a, d0, d1);
        g_pnum[base + qrow] = num;
        g_pden[base + qrow] = d0 + d1;
    }
    {
        float d0, d1, u0, u1;
        float4 num;
        unpack2(ab0, u0, u1); num.x = u0 + u1;
        unpack2(ab1, u0, u1); num.y = u0 + u1;
        unpack2(ab2, u0, u1); num.z = u0 + u1;
        unpack2(ab3, u0, u1); num.w = u0 + u1;
        unpack2(den_b, d0, d1);
        g_pnum[base + qrow + ATTN_TPB] = num;
        g_pden[base + qrow + ATTN_TPB] = d0 + d1;
    }
}

// ---------------------------------------------------------------------------
// Kernel 3: combine split partials -> ctx -> circuit(weights_C) -> out
// ---------------------------------------------------------------------------
__global__ void out_kernel(const float* __restrict__ wC, float4* __restrict__ out)
{
    int idx = blockIdx.x * blockDim.x + threadIdx.x;
    if (idx >= NROWS) return;

    float4 num = g_pnum[idx];
    float  den = g_pden[idx];
#pragma unroll
    for (int s = 1; s < NSPLIT; s++) {
        float4 n = g_pnum[s * NROWS + idx];
        num.x += n.x; num.y += n.y; num.z += n.z; num.w += n.w;
        den += g_pden[s * NROWS + idx];
    }
    float inv = __fdividef(1.f, den);
    float4 ctx = make_float4(num.x * inv, num.y * inv, num.z * inv, num.w * inv);

    float er[16], ei[16];
    embed(ctx, er, ei);

    float wc[4], ws[4];
    load_w(wC, wc, ws);
    out[idx] = layer_and_measure(er, ei, wc, ws);
}

// ---------------------------------------------------------------------------

extern "C" void kernel_launch(void* const* d_in, const int* in_sizes, int n_in,
                              void* d_out, int out_size)
{
    const float4* x  = (const float4*)d_in[0];
    const float*  wQ = (const float*)d_in[1];
    const float*  wK = (const float*)d_in[2];
    const float*  wV = (const float*)d_in[3];
    const float*  wC = (const float*)d_in[4];

    dim3 qkv_grid(NROWS / 128, 3);
    qkv_kernel<<<qkv_grid, 128>>>(x, wQ, wK, wV);

    dim3 grid(SS / (ATTN_TPB * 2), BB, NSPLIT);
    attn_kernel<<<grid, ATTN_TPB>>>();

    out_kernel<<<NROWS / 128, 128>>>(wC, (float4*)d_out);
}

// round 15
// speedup vs baseline: 1.2033x; 1.2033x over previous
#include <cuda_runtime.h>

#define BB 32
#define SS 2048
#define NROWS (BB * SS)
#define NSPLIT 16

// Scratch: __device__ globals (no allocation allowed in kernel_launch).
__device__ float4 g_Q[NROWS];            // pre-scaled by 0.5*log2(e)
// Pair-packed layouts: for key pair p (rows 2p, 2p+1):
//   g_Kp[2p]   = (k0.x, k1.x, k0.y, k1.y)
//   g_Kp[2p+1] = (k0.z, k1.z, k0.w, k1.w)
__device__ float4 g_Kp[NROWS];
__device__ float4 g_Vp[NROWS];
__device__ float4 g_pnum[NSPLIT * NROWS];  // partial sum(e*V)
__device__ float  g_pden[NSPLIT * NROWS];  // partial sum(e)

typedef unsigned long long ull;

// ---------------------------------------------------------------------------
// Packed f32x2 helpers (sm_103a FFMA2 path — ptxas won't auto-fuse from C++)
// ---------------------------------------------------------------------------
__device__ __forceinline__ ull pack2(float lo, float hi) {
    ull r; asm("mov.b64 %0, {%1, %2};" : "=l"(r) : "f"(lo), "f"(hi)); return r;
}
__device__ __forceinline__ void unpack2(ull v, float& lo, float& hi) {
    asm("mov.b64 {%0, %1}, %2;" : "=f"(lo), "=f"(hi) : "l"(v));
}
__device__ __forceinline__ ull fma2(ull a, ull b, ull c) {
    ull d; asm("fma.rn.f32x2 %0, %1, %2, %3;" : "=l"(d) : "l"(a), "l"(b), "l"(c)); return d;
}
__device__ __forceinline__ ull mul2(ull a, ull b) {
    ull d; asm("mul.rn.f32x2 %0, %1, %2;" : "=l"(d) : "l"(a), "l"(b)); return d;
}
__device__ __forceinline__ ull add2(ull a, ull b) {
    ull d; asm("add.rn.f32x2 %0, %1, %2;" : "=l"(d) : "l"(a), "l"(b)); return d;
}
// IEEE sign-flip of both packed halves: ALU pipe (LOP), not FMA.
__device__ __forceinline__ ull neg2(ull v) { return v ^ 0x8000000080000000ULL; }
__device__ __forceinline__ float fast_exp2(float x) {
    float y; asm("ex2.approx.ftz.f32 %0, %1;" : "=f"(y) : "f"(x)); return y;
}

// ---------------------------------------------------------------------------
// Scalar 16-dim statevector circuit (used by out_kernel).
// ---------------------------------------------------------------------------
template <int Q>
__device__ __forceinline__ void rx_gate(float sr[16], float si[16], float c, float sn) {
    const int m = 1 << (3 - Q);
#pragma unroll
    for (int i = 0; i < 16; i++) {
        if (!(i & m)) {
            const int j = i | m;
            float a0r = sr[i], a0i = si[i];
            float a1r = sr[j], a1i = si[j];
            sr[i] = c * a0r + sn * a1i;
            si[i] = c * a0i - sn * a1r;
            sr[j] = c * a1r + sn * a0i;
            si[j] = c * a1i - sn * a0r;
        }
    }
}

template <int Q>
__device__ __forceinline__ void cnot_gate(float sr[16], float si[16]) {
    const int cm = 1 << (3 - Q);
    const int tm = 1 << (3 - ((Q + 1) & 3));
#pragma unroll
    for (int i = 0; i < 16; i++) {
        if ((i & cm) && !(i & tm)) {
            const int j = i | tm;
            float t;
            t = sr[i]; sr[i] = sr[j]; sr[j] = t;
            t = si[i]; si[i] = si[j]; si[j] = t;
        }
    }
}

__device__ __forceinline__ float4 layer_and_measure(
    const float er[16], const float ei[16],
    const float wc[4], const float ws[4])
{
    float sr[16], si[16];
#pragma unroll
    for (int i = 0; i < 16; i++) { sr[i] = er[i]; si[i] = ei[i]; }

    rx_gate<0>(sr, si, wc[0], ws[0]);
    rx_gate<1>(sr, si, wc[1], ws[1]);
    rx_gate<2>(sr, si, wc[2], ws[2]);
    rx_gate<3>(sr, si, wc[3], ws[3]);
    cnot_gate<0>(sr, si);
    cnot_gate<1>(sr, si);
    cnot_gate<2>(sr, si);
    cnot_gate<3>(sr, si);

    float e0 = 0.f, e1 = 0.f, e2 = 0.f, e3 = 0.f;
#pragma unroll
    for (int i = 0; i < 16; i++) {
        float p = sr[i] * sr[i] + si[i] * si[i];
        e0 += (i & 8) ? -p : p;
        e1 += (i & 4) ? -p : p;
        e2 += (i & 2) ? -p : p;
        e3 += (i & 1) ? -p : p;
    }
    return make_float4(e0, e1, e2, e3);
}

__device__ __forceinline__ void embed(float4 ang, float er[16], float ei[16]) {
#pragma unroll
    for (int i = 0; i < 16; i++) { er[i] = 0.f; ei[i] = 0.f; }
    er[0] = 1.f;
    float c, sn;
    __sincosf(ang.x * 0.5f, &sn, &c); rx_gate<0>(er, ei, c, sn);
    __sincosf(ang.y * 0.5f, &sn, &c); rx_gate<1>(er, ei, c, sn);
    __sincosf(ang.z * 0.5f, &sn, &c); rx_gate<2>(er, ei, c, sn);
    __sincosf(ang.w * 0.5f, &sn, &c); rx_gate<3>(er, ei, c, sn);
}

__device__ __forceinline__ void load_w(const float* __restrict__ w, float wc[4], float ws[4]) {
#pragma unroll
    for (int i = 0; i < 4; i++) __sincosf(w[i] * 0.5f, &ws[i], &wc[i]);
}

// ---------------------------------------------------------------------------
// Packed (2-rows-per-thread) circuit: every op is f32x2 on (row0,row1) pairs.
// Same weights for both rows -> identical gate structure, no cross-lane mixing.
// ---------------------------------------------------------------------------
template <int Q>
__device__ __forceinline__ void rx_gate_p(ull Sr[16], ull Si[16],
                                          ull c2, ull s2, ull ns2) {
    const int m = 1 << (3 - Q);
#pragma unroll
    for (int i = 0; i < 16; i++) {
        if (!(i & m)) {
            const int j = i | m;
            ull a0r = Sr[i], a0i = Si[i];
            ull a1r = Sr[j], a1i = Si[j];
            Sr[i] = fma2(c2, a0r, mul2(s2,  a1i));   // c*a0r + s*a1i
            Si[i] = fma2(c2, a0i, mul2(ns2, a1r));   // c*a0i - s*a1r
            Sr[j] = fma2(c2, a1r, mul2(s2,  a0i));   // c*a1r + s*a0i
            Si[j] = fma2(c2, a1i, mul2(ns2, a0r));   // c*a1i - s*a0r
        }
    }
}

template <int Q>
__device__ __forceinline__ void cnot_gate_p(ull Sr[16], ull Si[16]) {
    const int cm = 1 << (3 - Q);
    const int tm = 1 << (3 - ((Q + 1) & 3));
#pragma unroll
    for (int i = 0; i < 16; i++) {
        if ((i & cm) && !(i & tm)) {
            const int j = i | tm;
            ull t;
            t = Sr[i]; Sr[i] = Sr[j]; Sr[j] = t;
            t = Si[i]; Si[i] = Si[j]; Si[j] = t;
        }
    }
}

// Closed-form embedded product state for 2 rows:
// amp(i) = (-j)^popcount(i) * prod_q (bit(i,3-q)==0 ? c_q : s_q)
__device__ __forceinline__ void embed_p(float4 a0, float4 a1,
                                        ull Er[16], ull Ei[16]) {
    float c0[4], s0[4], c1[4], s1[4];
    const float* p0 = &a0.x;
    const float* p1 = &a1.x;
#pragma unroll
    for (int q = 0; q < 4; q++) {
        __sincosf(p0[q] * 0.5f, &s0[q], &c0[q]);
        __sincosf(p1[q] * 0.5f, &s1[q], &c1[q]);
    }
    ull C[4], S[4];
#pragma unroll
    for (int q = 0; q < 4; q++) {
        C[q] = pack2(c0[q], c1[q]);
        S[q] = pack2(s0[q], s1[q]);
    }
    // hi index = (bit3, bit2) of i  (q0 -> bit3, q1 -> bit2)
    ull hi[4], lo[4];
    hi[0] = mul2(C[0], C[1]); hi[1] = mul2(C[0], S[1]);
    hi[2] = mul2(S[0], C[1]); hi[3] = mul2(S[0], S[1]);
    lo[0] = mul2(C[2], C[3]); lo[1] = mul2(C[2], S[3]);
    lo[2] = mul2(S[2], C[3]); lo[3] = mul2(S[2], S[3]);
#pragma unroll
    for (int i = 0; i < 16; i++) {
        ull m = mul2(hi[i >> 2], lo[i & 3]);
        const int k = __popc(i) & 3;
        if (k == 0)      { Er[i] = m;        Ei[i] = 0; }
        else if (k == 1) { Er[i] = 0;        Ei[i] = neg2(m); }
        else if (k == 2) { Er[i] = neg2(m);  Ei[i] = 0; }
        else             { Er[i] = 0;        Ei[i] = m; }
    }
}

// Measure <Z_q> packed: E[t] = (row0_e_t, row1_e_t).
__device__ __forceinline__ void measure_p(const ull Sr[16], const ull Si[16],
                                          ull E[4]) {
    ull pos[4] = {0, 0, 0, 0}, negs[4] = {0, 0, 0, 0};
#pragma unroll
    for (int i = 0; i < 16; i++) {
        ull p = fma2(Sr[i], Sr[i], mul2(Si[i], Si[i]));
        if (i & 8) negs[0] = add2(negs[0], p); else pos[0] = add2(pos[0], p);
        if (i & 4) negs[1] = add2(negs[1], p); else pos[1] = add2(pos[1], p);
        if (i & 2) negs[2] = add2(negs[2], p); else pos[2] = add2(pos[2], p);
        if (i & 1) negs[3] = add2(negs[3], p); else pos[3] = add2(pos[3], p);
    }
#pragma unroll
    for (int t = 0; t < 4; t++) E[t] = add2(pos[t], neg2(negs[t]));
}

// ---------------------------------------------------------------------------
// Kernel 1: x -> Q | K | V (which = blockIdx.y), 2 rows per thread, all math
// in packed f32x2 (halves the circuit FMA op count). Measured packed outputs
// ARE the pair-packed K/V layout -> two 16B vector stores.
// ---------------------------------------------------------------------------
__global__ void __launch_bounds__(128)
qkv_kernel(const float4* __restrict__ x,
           const float* __restrict__ wQ,
           const float* __restrict__ wK,
           const float* __restrict__ wV)
{
    const int pidx  = blockIdx.x * blockDim.x + threadIdx.x;  // pair index
    const int which = blockIdx.y;                             // 0=Q, 1=K, 2=V
    if (pidx >= NROWS / 2) return;

    ull Er[16], Ei[16];
    embed_p(x[2 * pidx], x[2 * pidx + 1], Er, Ei);

    const float* w = (which == 0) ? wQ : (which == 1) ? wK : wV;
    float wc[4], ws[4];
    load_w(w, wc, ws);
    ull C2[4], S2[4], NS2[4];
#pragma unroll
    for (int q = 0; q < 4; q++) {
        C2[q]  = pack2(wc[q], wc[q]);
        S2[q]  = pack2(ws[q], ws[q]);
        NS2[q] = pack2(-ws[q], -ws[q]);
    }

    rx_gate_p<0>(Er, Ei, C2[0], S2[0], NS2[0]);
    rx_gate_p<1>(Er, Ei, C2[1], S2[1], NS2[1]);
    rx_gate_p<2>(Er, Ei, C2[2], S2[2], NS2[2]);
    rx_gate_p<3>(Er, Ei, C2[3], S2[3], NS2[3]);
    cnot_gate_p<0>(Er, Ei);
    cnot_gate_p<1>(Er, Ei);
    cnot_gate_p<2>(Er, Ei);
    cnot_gate_p<3>(Er, Ei);

    ull E[4];
    measure_p(Er, Ei, E);

    if (which == 0) {
        const float scale = 0.5f * 1.4426950408889634f;  // 1/sqrt(E)*log2(e)
        ull sc = pack2(scale, scale);
        float r0[4], r1[4];
#pragma unroll
        for (int t = 0; t < 4; t++) {
            E[t] = mul2(E[t], sc);
            unpack2(E[t], r0[t], r1[t]);
        }
        g_Q[2 * pidx]     = make_float4(r0[0], r0[1], r0[2], r0[3]);
        g_Q[2 * pidx + 1] = make_float4(r1[0], r1[1], r1[2], r1[3]);
    } else {
        // E[0]=(k0.x,k1.x) E[1]=(k0.y,k1.y) E[2]=(k0.z,k1.z) E[3]=(k0.w,k1.w)
        // matches the pair-packed float4 layout exactly.
        ulonglong2* g = (which == 1) ? (ulonglong2*)g_Kp : (ulonglong2*)g_Vp;
        ulonglong2 v0; v0.x = E[0]; v0.y = E[1];
        ulonglong2 v1; v1.x = E[2]; v1.y = E[3];
        g[2 * pidx]     = v0;
        g[2 * pidx + 1] = v1;
    }
}

// ---------------------------------------------------------------------------
// Kernel 2: split-K flash attention partials (exact best-measured R10 config:
// TPB=128, QPT=2, NSPLIT=16, plain LDS loop — no pipelining).
// Raw exp2 softmax (scores in [-2.9,2.9]): partials combine exactly by sum.
// ---------------------------------------------------------------------------
#define ATTN_TPB   128
#define KEYS_SPLIT (SS / NSPLIT)        // 128 keys = 128 packed float4

__global__ void __launch_bounds__(ATTN_TPB)
attn_kernel()
{
    __shared__ float4 sK[KEYS_SPLIT];
    __shared__ float4 sV[KEYS_SPLIT];

    const int b     = blockIdx.y;
    const int split = blockIdx.z;
    const int t     = threadIdx.x;
    const int qrow  = b * SS + blockIdx.x * (ATTN_TPB * 2) + t;

    if (t < KEYS_SPLIT) {
        sK[t] = g_Kp[b * SS + split * KEYS_SPLIT + t];
        sV[t] = g_Vp[b * SS + split * KEYS_SPLIT + t];
    }

    float4 qa = g_Q[qrow];
    float4 qb = g_Q[qrow + ATTN_TPB];

    const ull qa_x = pack2(qa.x, qa.x), qa_y = pack2(qa.y, qa.y);
    const ull qa_z = pack2(qa.z, qa.z), qa_w = pack2(qa.w, qa.w);
    const ull qb_x = pack2(qb.x, qb.x), qb_y = pack2(qb.y, qb.y);
    const ull qb_z = pack2(qb.z, qb.z), qb_w = pack2(qb.w, qb.w);

    ull den_a = 0, den_b = 0;
    ull aa0 = 0, aa1 = 0, aa2 = 0, aa3 = 0;
    ull ab0 = 0, ab1 = 0, ab2 = 0, ab3 = 0;

    __syncthreads();

    const ulonglong2* kk = (const ulonglong2*)sK;
    const ulonglong2* vv = (const ulonglong2*)sV;

#pragma unroll 8
    for (int p = 0; p < KEYS_SPLIT / 2; p++) {
        ulonglong2 ka = kk[2 * p];      // (kx pair, ky pair)
        ulonglong2 kb = kk[2 * p + 1];  // (kz pair, kw pair)

        ull sa = fma2(qa_x, ka.x, fma2(qa_y, ka.y, fma2(qa_z, kb.x, mul2(qa_w, kb.y))));
        ull sb = fma2(qb_x, ka.x, fma2(qb_y, ka.y, fma2(qb_z, kb.x, mul2(qb_w, kb.y))));

        float s0, s1;
        unpack2(sa, s0, s1);
        ull ea = pack2(fast_exp2(s0), fast_exp2(s1));
        unpack2(sb, s0, s1);
        ull eb = pack2(fast_exp2(s0), fast_exp2(s1));

        den_a = add2(den_a, ea);
        den_b = add2(den_b, eb);

        ulonglong2 va = vv[2 * p];
        ulonglong2 vb = vv[2 * p + 1];

        aa0 = fma2(ea, va.x, aa0);
        aa1 = fma2(ea, va.y, aa1);
        aa2 = fma2(ea, vb.x, aa2);
        aa3 = fma2(ea, vb.y, aa3);
        ab0 = fma2(eb, va.x, ab0);
        ab1 = fma2(eb, va.y, ab1);
        ab2 = fma2(eb, vb.x, ab2);
        ab3 = fma2(eb, vb.y, ab3);
    }

    const int base = split * NROWS;
    {
        float d0, d1, u0, u1;
        float4 num;
        unpack2(aa0, u0, u1); num.x = u0 + u1;
        unpack2(aa1, u0, u1); num.y = u0 + u1;
        unpack2(aa2, u0, u1); num.z = u0 + u1;
        unpack2(aa3, u0, u1); num.w = u0 + u1;
        unpack2(den_a, d0, d1);
        g_pnum[base + qrow] = num;
        g_pden[base + qrow] = d0 + d1;
    }
    {
        float d0, d1, u0, u1;
        float4 num;
        unpack2(ab0, u0, u1); num.x = u0 + u1;
        unpack2(ab1, u0, u1); num.y = u0 + u1;
        unpack2(ab2, u0, u1); num.z = u0 + u1;
        unpack2(ab3, u0, u1); num.w = u0 + u1;
        unpack2(den_b, d0, d1);
        g_pnum[base + qrow + ATTN_TPB] = num;
        g_pden[base + qrow + ATTN_TPB] = d0 + d1;
    }
}

// ---------------------------------------------------------------------------
// Kernel 3: combine split partials -> ctx -> circuit(weights_C) -> out
// ---------------------------------------------------------------------------
__global__ void out_kernel(const float* __restrict__ wC, float4* __restrict__ out)
{
    int idx = blockIdx.x * blockDim.x + threadIdx.x;
    if (idx >= NROWS) return;

    float4 num = g_pnum[idx];
    float  den = g_pden[idx];
#pragma unroll
    for (int s = 1; s < NSPLIT; s++) {
        float4 n = g_pnum[s * NROWS + idx];
        num.x += n.x; num.y += n.y; num.z += n.z; num.w += n.w;
        den += g_pden[s * NROWS + idx];
    }
    float inv = __fdividef(1.f, den);
    float4 ctx = make_float4(num.x * inv, num.y * inv, num.z * inv, num.w * inv);

    float er[16], ei[16];
    embed(ctx, er, ei);

    float wc[4], ws[4];
    load_w(wC, wc, ws);
    out[idx] = layer_and_measure(er, ei, wc, ws);
}

// ---------------------------------------------------------------------------

extern "C" void kernel_launch(void* const* d_in, const int* in_sizes, int n_in,
                              void* d_out, int out_size)
{
    const float4* x  = (const float4*)d_in[0];
    const float*  wQ = (const float*)d_in[1];
    const float*  wK = (const float*)d_in[2];
    const float*  wV = (const float*)d_in[3];
    const float*  wC = (const float*)d_in[4];

    dim3 qkv_grid((NROWS / 2) / 128, 3);
    qkv_kernel<<<qkv_grid, 128>>>(x, wQ, wK, wV);

    dim3 grid(SS / (ATTN_TPB * 2), BB, NSPLIT);
    attn_kernel<<<grid, ATTN_TPB>>>();

    out_kernel<<<NROWS / 128, 128>>>(wC, (float4*)d_out);
}

// round 16
// speedup vs baseline: 1.2172x; 1.0116x over previous
#include <cuda_runtime.h>

#define BB 32
#define SS 2048
#define NROWS (BB * SS)
#define NSPLIT 16

// Scratch: __device__ globals (no allocation allowed in kernel_launch).
__device__ float4 g_Q[NROWS];            // pre-scaled by 0.5*log2(e)
// Pair-packed layouts: for key pair p (rows 2p, 2p+1):
//   g_Kp[2p]   = (k0.x, k1.x, k0.y, k1.y)
//   g_Kp[2p+1] = (k0.z, k1.z, k0.w, k1.w)
__device__ float4 g_Kp[NROWS];
__device__ float4 g_Vp[NROWS];
__device__ float4 g_accnum[NROWS];   // atomically accumulated sum(e*V)
__device__ float  g_accden[NROWS];   // atomically accumulated sum(e)

typedef unsigned long long ull;

// ---------------------------------------------------------------------------
// Packed f32x2 helpers (sm_103a FFMA2 path — ptxas won't auto-fuse from C++)
// ---------------------------------------------------------------------------
__device__ __forceinline__ ull pack2(float lo, float hi) {
    ull r; asm("mov.b64 %0, {%1, %2};" : "=l"(r) : "f"(lo), "f"(hi)); return r;
}
__device__ __forceinline__ void unpack2(ull v, float& lo, float& hi) {
    asm("mov.b64 {%0, %1}, %2;" : "=f"(lo), "=f"(hi) : "l"(v));
}
__device__ __forceinline__ ull fma2(ull a, ull b, ull c) {
    ull d; asm("fma.rn.f32x2 %0, %1, %2, %3;" : "=l"(d) : "l"(a), "l"(b), "l"(c)); return d;
}
__device__ __forceinline__ ull mul2(ull a, ull b) {
    ull d; asm("mul.rn.f32x2 %0, %1, %2;" : "=l"(d) : "l"(a), "l"(b)); return d;
}
__device__ __forceinline__ ull add2(ull a, ull b) {
    ull d; asm("add.rn.f32x2 %0, %1, %2;" : "=l"(d) : "l"(a), "l"(b)); return d;
}
// IEEE sign-flip of both packed halves: ALU pipe (LOP), not FMA.
__device__ __forceinline__ ull neg2(ull v) { return v ^ 0x8000000080000000ULL; }
__device__ __forceinline__ float fast_exp2(float x) {
    float y; asm("ex2.approx.ftz.f32 %0, %1;" : "=f"(y) : "f"(x)); return y;
}

// ---------------------------------------------------------------------------
// Scalar 16-dim statevector circuit (used by out_kernel).
// ---------------------------------------------------------------------------
template <int Q>
__device__ __forceinline__ void rx_gate(float sr[16], float si[16], float c, float sn) {
    const int m = 1 << (3 - Q);
#pragma unroll
    for (int i = 0; i < 16; i++) {
        if (!(i & m)) {
            const int j = i | m;
            float a0r = sr[i], a0i = si[i];
            float a1r = sr[j], a1i = si[j];
            sr[i] = c * a0r + sn * a1i;
            si[i] = c * a0i - sn * a1r;
            sr[j] = c * a1r + sn * a0i;
            si[j] = c * a1i - sn * a0r;
        }
    }
}

template <int Q>
__device__ __forceinline__ void cnot_gate(float sr[16], float si[16]) {
    const int cm = 1 << (3 - Q);
    const int tm = 1 << (3 - ((Q + 1) & 3));
#pragma unroll
    for (int i = 0; i < 16; i++) {
        if ((i & cm) && !(i & tm)) {
            const int j = i | tm;
            float t;
            t = sr[i]; sr[i] = sr[j]; sr[j] = t;
            t = si[i]; si[i] = si[j]; si[j] = t;
        }
    }
}

__device__ __forceinline__ float4 layer_and_measure(
    const float er[16], const float ei[16],
    const float wc[4], const float ws[4])
{
    float sr[16], si[16];
#pragma unroll
    for (int i = 0; i < 16; i++) { sr[i] = er[i]; si[i] = ei[i]; }

    rx_gate<0>(sr, si, wc[0], ws[0]);
    rx_gate<1>(sr, si, wc[1], ws[1]);
    rx_gate<2>(sr, si, wc[2], ws[2]);
    rx_gate<3>(sr, si, wc[3], ws[3]);
    cnot_gate<0>(sr, si);
    cnot_gate<1>(sr, si);
    cnot_gate<2>(sr, si);
    cnot_gate<3>(sr, si);

    float e0 = 0.f, e1 = 0.f, e2 = 0.f, e3 = 0.f;
#pragma unroll
    for (int i = 0; i < 16; i++) {
        float p = sr[i] * sr[i] + si[i] * si[i];
        e0 += (i & 8) ? -p : p;
        e1 += (i & 4) ? -p : p;
        e2 += (i & 2) ? -p : p;
        e3 += (i & 1) ? -p : p;
    }
    return make_float4(e0, e1, e2, e3);
}

__device__ __forceinline__ void embed(float4 ang, float er[16], float ei[16]) {
#pragma unroll
    for (int i = 0; i < 16; i++) { er[i] = 0.f; ei[i] = 0.f; }
    er[0] = 1.f;
    float c, sn;
    __sincosf(ang.x * 0.5f, &sn, &c); rx_gate<0>(er, ei, c, sn);
    __sincosf(ang.y * 0.5f, &sn, &c); rx_gate<1>(er, ei, c, sn);
    __sincosf(ang.z * 0.5f, &sn, &c); rx_gate<2>(er, ei, c, sn);
    __sincosf(ang.w * 0.5f, &sn, &c); rx_gate<3>(er, ei, c, sn);
}

__device__ __forceinline__ void load_w(const float* __restrict__ w, float wc[4], float ws[4]) {
#pragma unroll
    for (int i = 0; i < 4; i++) __sincosf(w[i] * 0.5f, &ws[i], &wc[i]);
}

// ---------------------------------------------------------------------------
// Packed (2-rows-per-thread) circuit: every op is f32x2 on (row0,row1) pairs.
// ---------------------------------------------------------------------------
template <int Q>
__device__ __forceinline__ void rx_gate_p(ull Sr[16], ull Si[16],
                                          ull c2, ull s2, ull ns2) {
    const int m = 1 << (3 - Q);
#pragma unroll
    for (int i = 0; i < 16; i++) {
        if (!(i & m)) {
            const int j = i | m;
            ull a0r = Sr[i], a0i = Si[i];
            ull a1r = Sr[j], a1i = Si[j];
            Sr[i] = fma2(c2, a0r, mul2(s2,  a1i));   // c*a0r + s*a1i
            Si[i] = fma2(c2, a0i, mul2(ns2, a1r));   // c*a0i - s*a1r
            Sr[j] = fma2(c2, a1r, mul2(s2,  a0i));   // c*a1r + s*a0i
            Si[j] = fma2(c2, a1i, mul2(ns2, a0r));   // c*a1i - s*a0r
        }
    }
}

template <int Q>
__device__ __forceinline__ void cnot_gate_p(ull Sr[16], ull Si[16]) {
    const int cm = 1 << (3 - Q);
    const int tm = 1 << (3 - ((Q + 1) & 3));
#pragma unroll
    for (int i = 0; i < 16; i++) {
        if ((i & cm) && !(i & tm)) {
            const int j = i | tm;
            ull t;
            t = Sr[i]; Sr[i] = Sr[j]; Sr[j] = t;
            t = Si[i]; Si[i] = Si[j]; Si[j] = t;
        }
    }
}

// Closed-form embedded product state for 2 rows:
// amp(i) = (-j)^popcount(i) * prod_q (bit(i,3-q)==0 ? c_q : s_q)
__device__ __forceinline__ void embed_p(float4 a0, float4 a1,
                                        ull Er[16], ull Ei[16]) {
    float c0[4], s0[4], c1[4], s1[4];
    const float* p0 = &a0.x;
    const float* p1 = &a1.x;
#pragma unroll
    for (int q = 0; q < 4; q++) {
        __sincosf(p0[q] * 0.5f, &s0[q], &c0[q]);
        __sincosf(p1[q] * 0.5f, &s1[q], &c1[q]);
    }
    ull C[4], S[4];
#pragma unroll
    for (int q = 0; q < 4; q++) {
        C[q] = pack2(c0[q], c1[q]);
        S[q] = pack2(s0[q], s1[q]);
    }
    ull hi[4], lo[4];
    hi[0] = mul2(C[0], C[1]); hi[1] = mul2(C[0], S[1]);
    hi[2] = mul2(S[0], C[1]); hi[3] = mul2(S[0], S[1]);
    lo[0] = mul2(C[2], C[3]); lo[1] = mul2(C[2], S[3]);
    lo[2] = mul2(S[2], C[3]); lo[3] = mul2(S[2], S[3]);
#pragma unroll
    for (int i = 0; i < 16; i++) {
        ull m = mul2(hi[i >> 2], lo[i & 3]);
        const int k = __popc(i) & 3;
        if (k == 0)      { Er[i] = m;        Ei[i] = 0; }
        else if (k == 1) { Er[i] = 0;        Ei[i] = neg2(m); }
        else if (k == 2) { Er[i] = neg2(m);  Ei[i] = 0; }
        else             { Er[i] = 0;        Ei[i] = m; }
    }
}

__device__ __forceinline__ void measure_p(const ull Sr[16], const ull Si[16],
                                          ull E[4]) {
    ull pos[4] = {0, 0, 0, 0}, negs[4] = {0, 0, 0, 0};
#pragma unroll
    for (int i = 0; i < 16; i++) {
        ull p = fma2(Sr[i], Sr[i], mul2(Si[i], Si[i]));
        if (i & 8) negs[0] = add2(negs[0], p); else pos[0] = add2(pos[0], p);
        if (i & 4) negs[1] = add2(negs[1], p); else pos[1] = add2(pos[1], p);
        if (i & 2) negs[2] = add2(negs[2], p); else pos[2] = add2(pos[2], p);
        if (i & 1) negs[3] = add2(negs[3], p); else pos[3] = add2(pos[3], p);
    }
#pragma unroll
    for (int t = 0; t < 4; t++) E[t] = add2(pos[t], neg2(negs[t]));
}

// ---------------------------------------------------------------------------
// Kernel 1: x -> Q | K | V (which = blockIdx.y), 2 rows per thread, packed
// f32x2 math. The Q branch ALSO zero-initializes the attention accumulators
// for its two rows (stream-ordered before attn's atomics; no extra launch).
// ---------------------------------------------------------------------------
__global__ void __launch_bounds__(128)
qkv_kernel(const float4* __restrict__ x,
           const float* __restrict__ wQ,
           const float* __restrict__ wK,
           const float* __restrict__ wV)
{
    const int pidx  = blockIdx.x * blockDim.x + threadIdx.x;  // pair index
    const int which = blockIdx.y;                             // 0=Q, 1=K, 2=V
    if (pidx >= NROWS / 2) return;

    ull Er[16], Ei[16];
    embed_p(x[2 * pidx], x[2 * pidx + 1], Er, Ei);

    const float* w = (which == 0) ? wQ : (which == 1) ? wK : wV;
    float wc[4], ws[4];
    load_w(w, wc, ws);
    ull C2[4], S2[4], NS2[4];
#pragma unroll
    for (int q = 0; q < 4; q++) {
        C2[q]  = pack2(wc[q], wc[q]);
        S2[q]  = pack2(ws[q], ws[q]);
        NS2[q] = pack2(-ws[q], -ws[q]);
    }

    rx_gate_p<0>(Er, Ei, C2[0], S2[0], NS2[0]);
    rx_gate_p<1>(Er, Ei, C2[1], S2[1], NS2[1]);
    rx_gate_p<2>(Er, Ei, C2[2], S2[2], NS2[2]);
    rx_gate_p<3>(Er, Ei, C2[3], S2[3], NS2[3]);
    cnot_gate_p<0>(Er, Ei);
    cnot_gate_p<1>(Er, Ei);
    cnot_gate_p<2>(Er, Ei);
    cnot_gate_p<3>(Er, Ei);

    ull E[4];
    measure_p(Er, Ei, E);

    if (which == 0) {
        const float scale = 0.5f * 1.4426950408889634f;  // 1/sqrt(E)*log2(e)
        ull sc = pack2(scale, scale);
        float r0[4], r1[4];
#pragma unroll
        for (int t = 0; t < 4; t++) {
            E[t] = mul2(E[t], sc);
            unpack2(E[t], r0[t], r1[t]);
        }
        g_Q[2 * pidx]     = make_float4(r0[0], r0[1], r0[2], r0[3]);
        g_Q[2 * pidx + 1] = make_float4(r1[0], r1[1], r1[2], r1[3]);

        // Zero the attention accumulators for these two rows.
        float4 z = make_float4(0.f, 0.f, 0.f, 0.f);
        g_accnum[2 * pidx]     = z;
        g_accnum[2 * pidx + 1] = z;
        g_accden[2 * pidx]     = 0.f;
        g_accden[2 * pidx + 1] = 0.f;
    } else {
        ulonglong2* g = (which == 1) ? (ulonglong2*)g_Kp : (ulonglong2*)g_Vp;
        ulonglong2 v0; v0.x = E[0]; v0.y = E[1];
        ulonglong2 v1; v1.x = E[2]; v1.y = E[3];
        g[2 * pidx]     = v0;
        g[2 * pidx + 1] = v1;
    }
}

// ---------------------------------------------------------------------------
// Kernel 2: split-K flash attention partials (best-measured R10 config:
// TPB=128, QPT=2, NSPLIT=16). Partials are REDUCED IN PLACE via
// red.global.add.f32 (atomicAdd, no return) instead of materialized —
// distinct per-query addresses parallelize across the 184 LTS slices.
// Raw exp2 softmax (scores in [-2.9,2.9]): sums combine exactly.
// ---------------------------------------------------------------------------
#define ATTN_TPB   128
#define KEYS_SPLIT (SS / NSPLIT)        // 128 keys = 128 packed float4

__global__ void __launch_bounds__(ATTN_TPB)
attn_kernel()
{
    __shared__ float4 sK[KEYS_SPLIT];
    __shared__ float4 sV[KEYS_SPLIT];

    const int b     = blockIdx.y;
    const int split = blockIdx.z;
    const int t     = threadIdx.x;
    const int qrow  = b * SS + blockIdx.x * (ATTN_TPB * 2) + t;

    if (t < KEYS_SPLIT) {
        sK[t] = g_Kp[b * SS + split * KEYS_SPLIT + t];
        sV[t] = g_Vp[b * SS + split * KEYS_SPLIT + t];
    }

    float4 qa = g_Q[qrow];
    float4 qb = g_Q[qrow + ATTN_TPB];

    const ull qa_x = pack2(qa.x, qa.x), qa_y = pack2(qa.y, qa.y);
    const ull qa_z = pack2(qa.z, qa.z), qa_w = pack2(qa.w, qa.w);
    const ull qb_x = pack2(qb.x, qb.x), qb_y = pack2(qb.y, qb.y);
    const ull qb_z = pack2(qb.z, qb.z), qb_w = pack2(qb.w, qb.w);

    ull den_a = 0, den_b = 0;
    ull aa0 = 0, aa1 = 0, aa2 = 0, aa3 = 0;
    ull ab0 = 0, ab1 = 0, ab2 = 0, ab3 = 0;

    __syncthreads();

    const ulonglong2* kk = (const ulonglong2*)sK;
    const ulonglong2* vv = (const ulonglong2*)sV;

#pragma unroll 8
    for (int p = 0; p < KEYS_SPLIT / 2; p++) {
        ulonglong2 ka = kk[2 * p];      // (kx pair, ky pair)
        ulonglong2 kb = kk[2 * p + 1];  // (kz pair, kw pair)

        ull sa = fma2(qa_x, ka.x, fma2(qa_y, ka.y, fma2(qa_z, kb.x, mul2(qa_w, kb.y))));
        ull sb = fma2(qb_x, ka.x, fma2(qb_y, ka.y, fma2(qb_z, kb.x, mul2(qb_w, kb.y))));

        float s0, s1;
        unpack2(sa, s0, s1);
        ull ea = pack2(fast_exp2(s0), fast_exp2(s1));
        unpack2(sb, s0, s1);
        ull eb = pack2(fast_exp2(s0), fast_exp2(s1));

        den_a = add2(den_a, ea);
        den_b = add2(den_b, eb);

        ulonglong2 va = vv[2 * p];
        ulonglong2 vb = vv[2 * p + 1];

        aa0 = fma2(ea, va.x, aa0);
        aa1 = fma2(ea, va.y, aa1);
        aa2 = fma2(ea, vb.x, aa2);
        aa3 = fma2(ea, vb.y, aa3);
        ab0 = fma2(eb, va.x, ab0);
        ab1 = fma2(eb, va.y, ab1);
        ab2 = fma2(eb, vb.x, ab2);
        ab3 = fma2(eb, vb.y, ab3);
    }

    {
        float d0, d1, u0, u1;
        float* nq = (float*)&g_accnum[qrow];
        unpack2(aa0, u0, u1); atomicAdd(nq + 0, u0 + u1);
        unpack2(aa1, u0, u1); atomicAdd(nq + 1, u0 + u1);
        unpack2(aa2, u0, u1); atomicAdd(nq + 2, u0 + u1);
        unpack2(aa3, u0, u1); atomicAdd(nq + 3, u0 + u1);
        unpack2(den_a, d0, d1); atomicAdd(&g_accden[qrow], d0 + d1);
    }
    {
        float d0, d1, u0, u1;
        float* nq = (float*)&g_accnum[qrow + ATTN_TPB];
        unpack2(ab0, u0, u1); atomicAdd(nq + 0, u0 + u1);
        unpack2(ab1, u0, u1); atomicAdd(nq + 1, u0 + u1);
        unpack2(ab2, u0, u1); atomicAdd(nq + 2, u0 + u1);
        unpack2(ab3, u0, u1); atomicAdd(nq + 3, u0 + u1);
        unpack2(den_b, d0, d1); atomicAdd(&g_accden[qrow + ATTN_TPB], d0 + d1);
    }
}

// ---------------------------------------------------------------------------
// Kernel 3: ctx = accnum/accden -> circuit(weights_C) -> out
// ---------------------------------------------------------------------------
__global__ void out_kernel(const float* __restrict__ wC, float4* __restrict__ out)
{
    int idx = blockIdx.x * blockDim.x + threadIdx.x;
    if (idx >= NROWS) return;

    float4 num = g_accnum[idx];
    float  den = g_accden[idx];
    float inv = __fdividef(1.f, den);
    float4 ctx = make_float4(num.x * inv, num.y * inv, num.z * inv, num.w * inv);

    float er[16], ei[16];
    embed(ctx, er, ei);

    float wc[4], ws[4];
    load_w(wC, wc, ws);
    out[idx] = layer_and_measure(er, ei, wc, ws);
}

// ---------------------------------------------------------------------------

extern "C" void kernel_launch(void* const* d_in, const int* in_sizes, int n_in,
                              void* d_out, int out_size)
{
    const float4* x  = (const float4*)d_in[0];
    const float*  wQ = (const float*)d_in[1];
    const float*  wK = (const float*)d_in[2];
    const float*  wV = (const float*)d_in[3];
    const float*  wC = (const float*)d_in[4];

    dim3 qkv_grid((NROWS / 2) / 128, 3);
    qkv_kernel<<<qkv_grid, 128>>>(x, wQ, wK, wV);

    dim3 grid(SS / (ATTN_TPB * 2), BB, NSPLIT);
    attn_kernel<<<grid, ATTN_TPB>>>();

    out_kernel<<<NROWS / 128, 128>>>(wC, (float4*)d_out);
}